// round 14
// baseline (speedup 1.0000x reference)
#include <cuda_runtime.h>

#define N_WAY   10
#define K_SHOT  5
#define PRJ     16
#define DIM     64
#define HW      49
#define N_SUP   800          // N_WAY * K_SHOT * PRJ
#define N_QRY   16000        // N_WAY * 100 * PRJ
#define NTRI    2080         // 64*65/2
#define PER_CLS 80           // K_SHOT * PRJ
#define XS_STR  68           // padded row stride for xs (16B-aligned, low conflict)
#define G_STR   65           // padded row stride for g (conflict-free column walk)

// -------- device scratch (static globals; no allocations) --------
__device__ float d_tvsup[N_SUP * NTRI];     // per-support-sample triu vectors (~6.7 MB)
__device__ float d_support[N_WAY * NTRI];   // class prototypes (83 KB)
__device__ float d_s2[N_WAY];               // prototype squared norms
__device__ float d_partial[64];             // loss partial sums
__device__ int   d_i64;                     // 1 if label buffer is int64, else int32

struct __align__(16) TVShared {
    float xs[HW * XS_STR];     // transposed sample: xs[m][i] = feat[i*49+m]
    float g [DIM * G_STR];     // Gram matrix (full, padded)
    float dg[DIM];             // diagonal of g
    float rmv[DIM];            // row means of dcov
    float part[256];           // row-sum partials
    float tmv;                 // total mean of dcov
};

// map linear triu index p -> row i  (row-major triu of 64x64, j>=i)
__device__ __forceinline__ int triu_row(int p) {
    int i = (int)(64.5f - sqrtf(4160.25f - 2.0f * (float)p));
    if (i < 0) i = 0;
    if (i > 63) i = 63;
    while (i > 0 && (i * (129 - i)) / 2 > p) --i;
    while (((i + 1) * (128 - i)) / 2 <= p) ++i;
    return i;
}

// Compute Gram, dcov row means and total mean for one sample. blockDim.x == 256.
__device__ void compute_v_stats(const float* __restrict__ fs, float et, TVShared& sh) {
    const int tid = threadIdx.x;

    // ---- load + transpose into smem ----
    for (int idx = tid; idx < DIM * HW; idx += 256) {
        int i = idx / HW;
        int m = idx - i * HW;
        sh.xs[m * XS_STR + i] = __ldg(fs + idx);
    }
    __syncthreads();

    // ---- full Gram: 16x16 grid of 4x4 register tiles ----
    const int i0 = (tid >> 4) << 2;
    const int j0 = (tid & 15) << 2;
    float acc[4][4];
    #pragma unroll
    for (int r = 0; r < 4; ++r)
        #pragma unroll
        for (int c = 0; c < 4; ++c) acc[r][c] = 0.f;

    const float* xrow = sh.xs;
    #pragma unroll 7
    for (int m = 0; m < HW; ++m) {
        const float4 a = *(const float4*)(xrow + i0);
        const float4 b = *(const float4*)(xrow + j0);
        acc[0][0] = fmaf(a.x, b.x, acc[0][0]); acc[0][1] = fmaf(a.x, b.y, acc[0][1]);
        acc[0][2] = fmaf(a.x, b.z, acc[0][2]); acc[0][3] = fmaf(a.x, b.w, acc[0][3]);
        acc[1][0] = fmaf(a.y, b.x, acc[1][0]); acc[1][1] = fmaf(a.y, b.y, acc[1][1]);
        acc[1][2] = fmaf(a.y, b.z, acc[1][2]); acc[1][3] = fmaf(a.y, b.w, acc[1][3]);
        acc[2][0] = fmaf(a.z, b.x, acc[2][0]); acc[2][1] = fmaf(a.z, b.y, acc[2][1]);
        acc[2][2] = fmaf(a.z, b.z, acc[2][2]); acc[2][3] = fmaf(a.z, b.w, acc[2][3]);
        acc[3][0] = fmaf(a.w, b.x, acc[3][0]); acc[3][1] = fmaf(a.w, b.y, acc[3][1]);
        acc[3][2] = fmaf(a.w, b.z, acc[3][2]); acc[3][3] = fmaf(a.w, b.w, acc[3][3]);
        xrow += XS_STR;
    }
    #pragma unroll
    for (int r = 0; r < 4; ++r)
        #pragma unroll
        for (int c = 0; c < 4; ++c)
            sh.g[(i0 + r) * G_STR + (j0 + c)] = acc[r][c];
    __syncthreads();

    // ---- diagonal ----
    if (tid < DIM) sh.dg[tid] = sh.g[tid * G_STR + tid];
    __syncthreads();

    // ---- dcov row sums (each row split across 4 thread groups) ----
    {
        const int i   = tid & 63;
        const int grp = tid >> 6;
        const float dgi = sh.dg[i];
        float s = 0.f;
        #pragma unroll
        for (int jj = 0; jj < 16; ++jj) {
            int j = (grp << 4) + jj;
            float d = dgi + sh.dg[j] - 2.f * sh.g[i * G_STR + j];
            s += sqrtf(fmaf(et, fmaxf(d, 0.f), 1e-5f));
        }
        sh.part[(grp << 6) + i] = s;
    }
    __syncthreads();
    if (tid < DIM) {
        float rs = sh.part[tid] + sh.part[64 + tid] + sh.part[128 + tid] + sh.part[192 + tid];
        sh.rmv[tid] = rs * (1.f / 64.f);
    }
    __syncthreads();
    if (tid < 32) {
        float t2 = sh.rmv[tid] + sh.rmv[tid + 32];
        #pragma unroll
        for (int off = 16; off; off >>= 1) t2 += __shfl_down_sync(0xffffffffu, t2, off);
        if (tid == 0) sh.tmv = t2 * (1.f / 64.f);   // tm = sum(rs)/4096
    }
    __syncthreads();
}

__device__ __forceinline__ float v_entry(const TVShared& sh, float et, int p) {
    int i = triu_row(p);
    int j = i + (p - (i * (129 - i)) / 2);
    float d  = sh.dg[i] + sh.dg[j] - 2.f * sh.g[i * G_STR + j];
    float dc = sqrtf(fmaf(et, fmaxf(d, 0.f), 1e-5f));
    return dc - sh.rmv[i] - sh.rmv[j] + sh.tmv;
}

// ---------------- kernel: detect int32 vs int64 label layout ----------------
__global__ void k_flag(const int* __restrict__ lab32) {
    int tid = threadIdx.x;
    int f = 0;
    for (int idx = 1 + 2 * tid; idx < N_QRY; idx += 2 * 512)
        if (lab32[idx] != 0) f = 1;
    f = __syncthreads_or(f);
    if (tid == 0) d_i64 = f ? 0 : 1;   // all-zero odd words => int64 little-endian
}

// ---------------- kernel: support sample triu vectors ----------------
__global__ __launch_bounds__(256) void k_support(const float* __restrict__ feat,
                                                 const float* __restrict__ temp) {
    __shared__ TVShared sh;
    const int b = blockIdx.x;                 // 0..799
    const float et = expf(temp[0]);
    compute_v_stats(feat + (size_t)b * (DIM * HW), et, sh);
    float* out = d_tvsup + (size_t)b * NTRI;
    for (int p = threadIdx.x; p < NTRI; p += 256)
        out[p] = v_entry(sh, et, p);
}

// ---------------- kernel: class prototypes + squared norms ----------------
__global__ __launch_bounds__(256) void k_redsup() {
    const int c   = blockIdx.x;               // 0..9
    const int tid = threadIdx.x;
    float s2loc = 0.f;
    for (int k = tid; k < NTRI; k += 256) {
        float s = 0.f;
        #pragma unroll 8
        for (int si = 0; si < PER_CLS; ++si)
            s += d_tvsup[(size_t)(c * PER_CLS + si) * NTRI + k];
        s *= (1.f / (float)PER_CLS);
        d_support[c * NTRI + k] = s;
        s2loc = fmaf(s, s, s2loc);
    }
    __shared__ float wsum[8];
    #pragma unroll
    for (int off = 16; off; off >>= 1) s2loc += __shfl_down_sync(0xffffffffu, s2loc, off);
    if ((tid & 31) == 0) wsum[tid >> 5] = s2loc;
    __syncthreads();
    if (tid == 0) {
        float t = 0.f;
        #pragma unroll
        for (int w = 0; w < 8; ++w) t += wsum[w];
        d_s2[c] = t;
    }
}

// ---------------- kernel: query tv + scores ----------------
__global__ __launch_bounds__(256) void k_query(const float* __restrict__ feat,
                                               const float* __restrict__ temp,
                                               float* __restrict__ score) {
    __shared__ TVShared sh;
    __shared__ float tv[NTRI];
    __shared__ float wred[8][11];
    const int q   = blockIdx.x;               // 0..15999
    const int tid = threadIdx.x;
    const float et = expf(temp[0]);

    compute_v_stats(feat + (size_t)(N_SUP + q) * (DIM * HW), et, sh);

    for (int p = tid; p < NTRI; p += 256)
        tv[p] = v_entry(sh, et, p);
    __syncthreads();

    float accq = 0.f;
    float accm[N_WAY];
    #pragma unroll
    for (int m = 0; m < N_WAY; ++m) accm[m] = 0.f;

    for (int k = tid; k < NTRI; k += 256) {
        float t = tv[k];
        accq = fmaf(t, t, accq);
        #pragma unroll
        for (int m = 0; m < N_WAY; ++m)
            accm[m] = fmaf(t, __ldg(&d_support[m * NTRI + k]), accm[m]);
    }

    // warp-level reduce of 11 values
    #pragma unroll
    for (int off = 16; off; off >>= 1) {
        accq += __shfl_down_sync(0xffffffffu, accq, off);
        #pragma unroll
        for (int m = 0; m < N_WAY; ++m)
            accm[m] += __shfl_down_sync(0xffffffffu, accm[m], off);
    }
    if ((tid & 31) == 0) {
        int w = tid >> 5;
        wred[w][10] = accq;
        #pragma unroll
        for (int m = 0; m < N_WAY; ++m) wred[w][m] = accm[m];
    }
    __syncthreads();
    if (tid == 0) {
        float q2 = 0.f;
        #pragma unroll
        for (int w = 0; w < 8; ++w) q2 += wred[w][10];
        #pragma unroll
        for (int m = 0; m < N_WAY; ++m) {
            float dm = 0.f;
            #pragma unroll
            for (int w = 0; w < 8; ++w) dm += wred[w][m];
            score[(size_t)q * N_WAY + m] = -(q2 + d_s2[m] - 2.f * dm);
        }
    }
}

// ---------------- kernel: per-row NLL partials ----------------
__global__ __launch_bounds__(256) void k_loss(const float* __restrict__ score,
                                              const void* __restrict__ label) {
    const int n   = blockIdx.x * 256 + threadIdx.x;
    const int tid = threadIdx.x;
    float val = 0.f;
    if (n < N_QRY) {
        float s[N_WAY];
        float mx = -1e30f;
        #pragma unroll
        for (int m = 0; m < N_WAY; ++m) {
            s[m] = score[(size_t)n * N_WAY + m];
            mx = fmaxf(mx, s[m]);
        }
        float se = 0.f;
        #pragma unroll
        for (int m = 0; m < N_WAY; ++m) se += expf(s[m] - mx);
        float lse = mx + logf(se);
        int lab = d_i64 ? (int)((const long long*)label)[n]
                        : ((const int*)label)[n];
        val = s[lab] - lse;
    }
    __shared__ float wsum[8];
    #pragma unroll
    for (int off = 16; off; off >>= 1) val += __shfl_down_sync(0xffffffffu, val, off);
    if ((tid & 31) == 0) wsum[tid >> 5] = val;
    __syncthreads();
    if (tid == 0) {
        float t = 0.f;
        #pragma unroll
        for (int w = 0; w < 8; ++w) t += wsum[w];
        d_partial[blockIdx.x] = t;
    }
}

// ---------------- kernel: final loss ----------------
__global__ void k_final(float* __restrict__ out, int nblk) {
    int tid = threadIdx.x;   // 32 threads
    float s = 0.f;
    for (int idx = tid; idx < nblk; idx += 32) s += d_partial[idx];
    #pragma unroll
    for (int off = 16; off; off >>= 1) s += __shfl_down_sync(0xffffffffu, s, off);
    if (tid == 0) out[(size_t)N_QRY * N_WAY] = -s * (1.f / (float)N_QRY);
}

// ---------------- launch ----------------
extern "C" void kernel_launch(void* const* d_in, const int* in_sizes, int n_in,
                              void* d_out, int out_size) {
    const float* feat  = (const float*)d_in[0];
    const float* temp  = (const float*)d_in[1];
    const void*  label = d_in[2];
    float* out = (float*)d_out;
    (void)in_sizes; (void)n_in; (void)out_size;

    const int loss_blocks = (N_QRY + 255) / 256;   // 63

    k_flag   <<<1, 512>>>((const int*)label);
    k_support<<<N_SUP, 256>>>(feat, temp);
    k_redsup <<<N_WAY, 256>>>();
    k_query  <<<N_QRY, 256>>>(feat, temp, out);
    k_loss   <<<loss_blocks, 256>>>(out, label);
    k_final  <<<1, 32>>>(out, loss_blocks);
}

// round 15
// speedup vs baseline: 1.1379x; 1.1379x over previous
#include <cuda_runtime.h>

#define N_WAY   10
#define DIM     64
#define HW      49
#define N_SUP   800
#define N_QRY   16000
#define NTRI    2080         // 64*65/2 (triu incl diag)
#define NSTRICT 2016         // strict upper triangle
#define PER_CLS 80
#define XS_STR  68           // padded row stride for xs
#define G_STR   65           // padded row stride for g (conflict-free columns)

// -------- device scratch (static globals; no allocations) --------
__device__ float d_tvsup[N_SUP * NTRI];     // per-support-sample packed tv (strict | diag)
__device__ float d_support[N_WAY * NTRI];   // prototypes, packed (strict 2016 | diag 64)
__device__ float d_s2[N_WAY];
__device__ float d_partial[64];
__device__ int   d_i64;
__device__ __align__(16) unsigned short d_idx[NSTRICT];  // packed (j<<6)|i per strict-p

// ============ shared helpers ============

__device__ __forceinline__ void load_xs(const float* __restrict__ fs,
                                        float* __restrict__ xs, int tid) {
    for (int idx = tid; idx < DIM * HW; idx += 256) {
        int i = idx / HW;
        int m = idx - i * HW;
        xs[m * XS_STR + i] = __ldg(fs + idx);
    }
}

// full 64x64 Gram from transposed xs; 16x16 grid of 4x4 register tiles
__device__ __forceinline__ void gram64(const float* __restrict__ xs,
                                       float* __restrict__ g, int tid) {
    const int i0 = (tid >> 4) << 2;
    const int j0 = (tid & 15) << 2;
    float acc[4][4];
    #pragma unroll
    for (int r = 0; r < 4; ++r)
        #pragma unroll
        for (int c = 0; c < 4; ++c) acc[r][c] = 0.f;

    const float* xrow = xs;
    #pragma unroll 7
    for (int m = 0; m < HW; ++m) {
        const float4 a = *(const float4*)(xrow + i0);
        const float4 b = *(const float4*)(xrow + j0);
        acc[0][0] = fmaf(a.x, b.x, acc[0][0]); acc[0][1] = fmaf(a.x, b.y, acc[0][1]);
        acc[0][2] = fmaf(a.x, b.z, acc[0][2]); acc[0][3] = fmaf(a.x, b.w, acc[0][3]);
        acc[1][0] = fmaf(a.y, b.x, acc[1][0]); acc[1][1] = fmaf(a.y, b.y, acc[1][1]);
        acc[1][2] = fmaf(a.y, b.z, acc[1][2]); acc[1][3] = fmaf(a.y, b.w, acc[1][3]);
        acc[2][0] = fmaf(a.z, b.x, acc[2][0]); acc[2][1] = fmaf(a.z, b.y, acc[2][1]);
        acc[2][2] = fmaf(a.z, b.z, acc[2][2]); acc[2][3] = fmaf(a.z, b.w, acc[2][3]);
        acc[3][0] = fmaf(a.w, b.x, acc[3][0]); acc[3][1] = fmaf(a.w, b.y, acc[3][1]);
        acc[3][2] = fmaf(a.w, b.z, acc[3][2]); acc[3][3] = fmaf(a.w, b.w, acc[3][3]);
        xrow += XS_STR;
    }
    #pragma unroll
    for (int r = 0; r < 4; ++r)
        #pragma unroll
        for (int c = 0; c < 4; ++c)
            g[(i0 + r) * G_STR + (j0 + c)] = acc[r][c];
}

// ============ init: strict-upper (i,j) index table ============
__global__ void k_idx() {
    int i = threadIdx.x;   // 64 threads
    if (i < 63) {
        int base = (i * (127 - i)) >> 1;
        for (int j = i + 1; j < 64; ++j)
            d_idx[base + j - i - 1] = (unsigned short)((j << 6) | i);
    }
}

// ============ label dtype detection ============
__global__ void k_flag(const int* __restrict__ lab32) {
    int tid = threadIdx.x;
    int f = 0;
    for (int idx = 1 + 2 * tid; idx < N_QRY; idx += 2 * 512)
        if (lab32[idx] != 0) f = 1;
    f = __syncthreads_or(f);
    if (tid == 0) d_i64 = f ? 0 : 1;
}

// ============ support: packed centered tv per sample ============
struct __align__(16) SupShared {
    float xs[HW * XS_STR];
    float g [DIM * G_STR];
    float dg[DIM];
    float rmv[DIM];
    float part[256];
    float tmv;
};

__global__ __launch_bounds__(256) void k_support(const float* __restrict__ feat,
                                                 const float* __restrict__ temp) {
    __shared__ SupShared sh;
    const int b   = blockIdx.x;
    const int tid = threadIdx.x;
    const float et = expf(temp[0]);

    load_xs(feat + (size_t)b * (DIM * HW), sh.xs, tid);
    __syncthreads();
    gram64(sh.xs, sh.g, tid);
    __syncthreads();
    if (tid < DIM) sh.dg[tid] = sh.g[tid * G_STR + tid];
    __syncthreads();

    // dcov row sums
    {
        const int i = tid & 63, grp = tid >> 6;
        const float dgi = sh.dg[i];
        float s = 0.f;
        #pragma unroll
        for (int jj = 0; jj < 16; ++jj) {
            int j = (grp << 4) + jj;
            float d = dgi + sh.dg[j] - 2.f * sh.g[i * G_STR + j];
            s += sqrtf(fmaf(et, fmaxf(d, 0.f), 1e-5f));
        }
        sh.part[(grp << 6) + i] = s;
    }
    __syncthreads();
    if (tid < DIM) {
        float rs = sh.part[tid] + sh.part[64 + tid] + sh.part[128 + tid] + sh.part[192 + tid];
        sh.rmv[tid] = rs * (1.f / 64.f);
    }
    __syncthreads();
    if (tid < 32) {
        float t2 = sh.rmv[tid] + sh.rmv[tid + 32];
        #pragma unroll
        for (int off = 16; off; off >>= 1) t2 += __shfl_down_sync(0xffffffffu, t2, off);
        if (tid == 0) sh.tmv = t2 * (1.f / 64.f);
    }
    __syncthreads();

    float* out = d_tvsup + (size_t)b * NTRI;
    const float tmv = sh.tmv;
    for (int p = tid; p < NSTRICT; p += 256) {
        unsigned short id = d_idx[p];
        int i = id & 63, j = id >> 6;
        float d  = sh.dg[i] + sh.dg[j] - 2.f * sh.g[i * G_STR + j];
        float dc = sqrtf(fmaf(et, fmaxf(d, 0.f), 1e-5f));
        out[p] = dc - sh.rmv[i] - sh.rmv[j] + tmv;
    }
    if (tid < DIM)
        out[NSTRICT + tid] = sqrtf(1e-5f) - 2.f * sh.rmv[tid] + tmv;
}

// ============ class prototypes ============
__global__ __launch_bounds__(256) void k_redsup() {
    const int c = blockIdx.x;
    const int k = blockIdx.y * 256 + threadIdx.x;
    if (k >= NTRI) return;
    const float* base = d_tvsup + (size_t)c * PER_CLS * NTRI + k;
    float s = 0.f;
    #pragma unroll 8
    for (int si = 0; si < PER_CLS; ++si) s += base[(size_t)si * NTRI];
    d_support[c * NTRI + k] = s * (1.f / (float)PER_CLS);
}

__global__ __launch_bounds__(256) void k_s2() {
    const int c = blockIdx.x, tid = threadIdx.x;
    float a = 0.f;
    for (int k = tid; k < NTRI; k += 256) {
        float v = d_support[c * NTRI + k];
        a = fmaf(v, v, a);
    }
    __shared__ float wsum[8];
    #pragma unroll
    for (int off = 16; off; off >>= 1) a += __shfl_down_sync(0xffffffffu, a, off);
    if ((tid & 31) == 0) wsum[tid >> 5] = a;
    __syncthreads();
    if (tid == 0) {
        float t = 0.f;
        #pragma unroll
        for (int w = 0; w < 8; ++w) t += wsum[w];
        d_s2[c] = t;
    }
}

// ============ query: fused dq / q2 / cross ============
struct __align__(16) QShared {
    union {
        float xs [HW * XS_STR];   // live during gram
        float dqt[NSTRICT];       // packed strict-upper dq, live after
    } u;
    float g [DIM * G_STR];
    float dg[DIM];
    float rq[DIM];                // row means of dq
    float part[256];
    float tq;
    float wred[8][11];
};

__global__ __launch_bounds__(256) void k_query(const float* __restrict__ feat,
                                               const float* __restrict__ temp,
                                               float* __restrict__ score) {
    __shared__ QShared sh;
    const int q   = blockIdx.x;
    const int tid = threadIdx.x;
    const float et = expf(temp[0]);

    load_xs(feat + (size_t)(N_SUP + q) * (DIM * HW), sh.u.xs, tid);
    __syncthreads();
    gram64(sh.u.xs, sh.g, tid);
    __syncthreads();
    if (tid < DIM) sh.dg[tid] = sh.g[tid * G_STR + tid];
    __syncthreads();

    // dq pass: sqrt all 4096, row sums, pack strict upper into dqt (xs is dead)
    {
        const int i = tid & 63, grp = tid >> 6;
        const int jb = grp << 4;
        const float dgi = sh.dg[i];
        const int rowoff = (i * (127 - i)) >> 1;
        float s = 0.f;
        #pragma unroll
        for (int jj = 0; jj < 16; ++jj) {
            int j = jb + jj;
            float d  = dgi + sh.dg[j] - 2.f * sh.g[i * G_STR + j];
            float dq = sqrtf(fmaf(et, fmaxf(d, 0.f), 1e-5f));
            s += dq;
            if (j > i) sh.u.dqt[rowoff + j - i - 1] = dq;
        }
        sh.part[(grp << 6) + i] = s;
    }
    __syncthreads();
    if (tid < DIM) {
        float rs = sh.part[tid] + sh.part[64 + tid] + sh.part[128 + tid] + sh.part[192 + tid];
        sh.rq[tid] = rs * (1.f / 64.f);
    }
    __syncthreads();
    if (tid < 32) {
        float t2 = sh.rq[tid] + sh.rq[tid + 32];
        #pragma unroll
        for (int off = 16; off; off >>= 1) t2 += __shfl_down_sync(0xffffffffu, t2, off);
        if (tid == 0) sh.tq = t2 * (1.f / 64.f);
    }
    __syncthreads();
    const float tqv = sh.tq;

    // cross pass over strict upper, float4-vectorized (504 groups of 4)
    float accm[N_WAY];
    #pragma unroll
    for (int m = 0; m < N_WAY; ++m) accm[m] = 0.f;
    float q2a = 0.f;

    #pragma unroll
    for (int it = 0; it < 2; ++it) {
        int gidx = (it << 8) + tid;
        if (gidx < NSTRICT / 4) {
            int p = gidx << 2;
            ushort4 id4 = *(const ushort4*)(d_idx + p);
            float4  dq4 = *(const float4*)(sh.u.dqt + p);

            // q2 (centered values only needed here)
            {
                float v0 = dq4.x - sh.rq[id4.x & 63] - sh.rq[id4.x >> 6] + tqv;
                float v1 = dq4.y - sh.rq[id4.y & 63] - sh.rq[id4.y >> 6] + tqv;
                float v2 = dq4.z - sh.rq[id4.z & 63] - sh.rq[id4.z >> 6] + tqv;
                float v3 = dq4.w - sh.rq[id4.w & 63] - sh.rq[id4.w >> 6] + tqv;
                q2a = fmaf(v0, v0, q2a);
                q2a = fmaf(v1, v1, q2a);
                q2a = fmaf(v2, v2, q2a);
                q2a = fmaf(v3, v3, q2a);
            }
            // cross terms use RAW dq (support rows are zero-sum over full matrix)
            #pragma unroll
            for (int m = 0; m < N_WAY; ++m) {
                float4 sv = __ldg((const float4*)(d_support + m * NTRI + p));
                accm[m] = fmaf(dq4.x, sv.x, accm[m]);
                accm[m] = fmaf(dq4.y, sv.y, accm[m]);
                accm[m] = fmaf(dq4.z, sv.z, accm[m]);
                accm[m] = fmaf(dq4.w, sv.w, accm[m]);
            }
        }
    }

    // diagonal contributions folded into same accumulators
    if (tid < DIM) {
        float sq  = sqrtf(1e-5f);
        float rqi = sh.rq[tid];
        float vqd = sq - 2.f * rqi + tqv;          // centered diag value
        float w   = sq - rqi + 0.5f * tqv;          // 0.5*(dq_ii + vq_ii)
        q2a = fmaf(vqd, vqd, q2a);
        #pragma unroll
        for (int m = 0; m < N_WAY; ++m)
            accm[m] = fmaf(w, __ldg(d_support + m * NTRI + NSTRICT + tid), accm[m]);
    }

    // block reduction: 11 values
    #pragma unroll
    for (int off = 16; off; off >>= 1) {
        q2a += __shfl_down_sync(0xffffffffu, q2a, off);
        #pragma unroll
        for (int m = 0; m < N_WAY; ++m)
            accm[m] += __shfl_down_sync(0xffffffffu, accm[m], off);
    }
    if ((tid & 31) == 0) {
        int w = tid >> 5;
        sh.wred[w][10] = q2a;
        #pragma unroll
        for (int m = 0; m < N_WAY; ++m) sh.wred[w][m] = accm[m];
    }
    __syncthreads();
    if (tid == 0) {
        float q2 = 0.f;
        #pragma unroll
        for (int w = 0; w < 8; ++w) q2 += sh.wred[w][10];
        #pragma unroll
        for (int m = 0; m < N_WAY; ++m) {
            float dot = 0.f;
            #pragma unroll
            for (int w = 0; w < 8; ++w) dot += sh.wred[w][m];
            score[(size_t)q * N_WAY + m] = -(q2 + d_s2[m] - 2.f * dot);
        }
    }
}

// ============ loss ============
__global__ __launch_bounds__(256) void k_loss(const float* __restrict__ score,
                                              const void* __restrict__ label) {
    const int n   = blockIdx.x * 256 + threadIdx.x;
    const int tid = threadIdx.x;
    float val = 0.f;
    if (n < N_QRY) {
        float s[N_WAY];
        float mx = -1e30f;
        #pragma unroll
        for (int m = 0; m < N_WAY; ++m) {
            s[m] = score[(size_t)n * N_WAY + m];
            mx = fmaxf(mx, s[m]);
        }
        float se = 0.f;
        #pragma unroll
        for (int m = 0; m < N_WAY; ++m) se += expf(s[m] - mx);
        float lse = mx + logf(se);
        int lab = d_i64 ? (int)((const long long*)label)[n]
                        : ((const int*)label)[n];
        val = s[lab] - lse;
    }
    __shared__ float wsum[8];
    #pragma unroll
    for (int off = 16; off; off >>= 1) val += __shfl_down_sync(0xffffffffu, val, off);
    if ((tid & 31) == 0) wsum[tid >> 5] = val;
    __syncthreads();
    if (tid == 0) {
        float t = 0.f;
        #pragma unroll
        for (int w = 0; w < 8; ++w) t += wsum[w];
        d_partial[blockIdx.x] = t;
    }
}

__global__ void k_final(float* __restrict__ out, int nblk) {
    int tid = threadIdx.x;   // 32
    float s = 0.f;
    for (int idx = tid; idx < nblk; idx += 32) s += d_partial[idx];
    #pragma unroll
    for (int off = 16; off; off >>= 1) s += __shfl_down_sync(0xffffffffu, s, off);
    if (tid == 0) out[(size_t)N_QRY * N_WAY] = -s * (1.f / (float)N_QRY);
}

// ============ launch ============
extern "C" void kernel_launch(void* const* d_in, const int* in_sizes, int n_in,
                              void* d_out, int out_size) {
    const float* feat  = (const float*)d_in[0];
    const float* temp  = (const float*)d_in[1];
    const void*  label = d_in[2];
    float* out = (float*)d_out;
    (void)in_sizes; (void)n_in; (void)out_size;

    const int loss_blocks = (N_QRY + 255) / 256;   // 63

    k_idx    <<<1, 64>>>();
    k_flag   <<<1, 512>>>((const int*)label);
    k_support<<<N_SUP, 256>>>(feat, temp);
    k_redsup <<<dim3(N_WAY, (NTRI + 255) / 256), 256>>>();
    k_s2     <<<N_WAY, 256>>>();
    k_query  <<<N_QRY, 256>>>(feat, temp, out);
    k_loss   <<<loss_blocks, 256>>>(out, label);
    k_final  <<<1, 32>>>(out, loss_blocks);
}

// round 16
// speedup vs baseline: 1.1507x; 1.0113x over previous
#include <cuda_runtime.h>

#define N_WAY   10
#define DIM     64
#define HW      49
#define N_SUP   800
#define N_QRY   16000
#define NTRI    2080         // 64*65/2 (triu incl diag)
#define NSTRICT 2016         // strict upper triangle
#define PER_CLS 80
#define XS_STR  68           // padded row stride for xs
#define G_STR   65           // padded row stride for g (conflict-free columns)

// -------- device scratch (static globals; no allocations) --------
__device__ float d_tvsup[N_SUP * NTRI];     // per-support-sample packed tv (strict | diag)
__device__ float d_support[N_WAY * NTRI];   // prototypes, packed (strict 2016 | diag 64)
__device__ float d_s2[N_WAY];
__device__ float d_partial[64];
__device__ int   d_i64;
__device__ __align__(16) unsigned short d_idx[NSTRICT];  // packed (j<<6)|i per strict-p

// ============ shared helpers ============

__device__ __forceinline__ void load_xs(const float* __restrict__ fs,
                                        float* __restrict__ xs, int tid) {
    for (int idx = tid; idx < DIM * HW; idx += 256) {
        int i = idx / HW;
        int m = idx - i * HW;
        xs[m * XS_STR + i] = __ldg(fs + idx);
    }
}

// full 64x64 Gram from transposed xs; 16x16 grid of 4x4 register tiles
__device__ __forceinline__ void gram64(const float* __restrict__ xs,
                                       float* __restrict__ g, int tid) {
    const int i0 = (tid >> 4) << 2;
    const int j0 = (tid & 15) << 2;
    float acc[4][4];
    #pragma unroll
    for (int r = 0; r < 4; ++r)
        #pragma unroll
        for (int c = 0; c < 4; ++c) acc[r][c] = 0.f;

    const float* xrow = xs;
    #pragma unroll 7
    for (int m = 0; m < HW; ++m) {
        const float4 a = *(const float4*)(xrow + i0);
        const float4 b = *(const float4*)(xrow + j0);
        acc[0][0] = fmaf(a.x, b.x, acc[0][0]); acc[0][1] = fmaf(a.x, b.y, acc[0][1]);
        acc[0][2] = fmaf(a.x, b.z, acc[0][2]); acc[0][3] = fmaf(a.x, b.w, acc[0][3]);
        acc[1][0] = fmaf(a.y, b.x, acc[1][0]); acc[1][1] = fmaf(a.y, b.y, acc[1][1]);
        acc[1][2] = fmaf(a.y, b.z, acc[1][2]); acc[1][3] = fmaf(a.y, b.w, acc[1][3]);
        acc[2][0] = fmaf(a.z, b.x, acc[2][0]); acc[2][1] = fmaf(a.z, b.y, acc[2][1]);
        acc[2][2] = fmaf(a.z, b.z, acc[2][2]); acc[2][3] = fmaf(a.z, b.w, acc[2][3]);
        acc[3][0] = fmaf(a.w, b.x, acc[3][0]); acc[3][1] = fmaf(a.w, b.y, acc[3][1]);
        acc[3][2] = fmaf(a.w, b.z, acc[3][2]); acc[3][3] = fmaf(a.w, b.w, acc[3][3]);
        xrow += XS_STR;
    }
    #pragma unroll
    for (int r = 0; r < 4; ++r)
        #pragma unroll
        for (int c = 0; c < 4; ++c)
            g[(i0 + r) * G_STR + (j0 + c)] = acc[r][c];
}

// ============ init: strict-upper (i,j) index table ============
__global__ void k_idx() {
    int i = threadIdx.x;   // 64 threads
    if (i < 63) {
        int base = (i * (127 - i)) >> 1;
        for (int j = i + 1; j < 64; ++j)
            d_idx[base + j - i - 1] = (unsigned short)((j << 6) | i);
    }
}

// ============ label dtype detection ============
__global__ void k_flag(const int* __restrict__ lab32) {
    int tid = threadIdx.x;
    int f = 0;
    for (int idx = 1 + 2 * tid; idx < N_QRY; idx += 2 * 512)
        if (lab32[idx] != 0) f = 1;
    f = __syncthreads_or(f);
    if (tid == 0) d_i64 = f ? 0 : 1;
}

// ============ support: packed centered tv per sample ============
struct __align__(16) SupShared {
    float xs[HW * XS_STR];
    float g [DIM * G_STR];
    float dg[DIM];
    float rmv[DIM];
    float part[256];
    float tmv;
};

__global__ __launch_bounds__(256) void k_support(const float* __restrict__ feat,
                                                 const float* __restrict__ temp) {
    __shared__ SupShared sh;
    const int b   = blockIdx.x;
    const int tid = threadIdx.x;
    const float et = expf(temp[0]);

    load_xs(feat + (size_t)b * (DIM * HW), sh.xs, tid);
    __syncthreads();
    gram64(sh.xs, sh.g, tid);
    __syncthreads();
    if (tid < DIM) sh.dg[tid] = sh.g[tid * G_STR + tid];
    __syncthreads();

    // dcov row sums
    {
        const int i = tid & 63, grp = tid >> 6;
        const float dgi = sh.dg[i];
        float s = 0.f;
        #pragma unroll
        for (int jj = 0; jj < 16; ++jj) {
            int j = (grp << 4) + jj;
            float d = dgi + sh.dg[j] - 2.f * sh.g[i * G_STR + j];
            s += sqrtf(fmaf(et, fmaxf(d, 0.f), 1e-5f));
        }
        sh.part[(grp << 6) + i] = s;
    }
    __syncthreads();
    if (tid < DIM) {
        float rs = sh.part[tid] + sh.part[64 + tid] + sh.part[128 + tid] + sh.part[192 + tid];
        sh.rmv[tid] = rs * (1.f / 64.f);
    }
    __syncthreads();
    if (tid < 32) {
        float t2 = sh.rmv[tid] + sh.rmv[tid + 32];
        #pragma unroll
        for (int off = 16; off; off >>= 1) t2 += __shfl_down_sync(0xffffffffu, t2, off);
        if (tid == 0) sh.tmv = t2 * (1.f / 64.f);
    }
    __syncthreads();

    float* out = d_tvsup + (size_t)b * NTRI;
    const float tmv = sh.tmv;
    for (int p = tid; p < NSTRICT; p += 256) {
        unsigned short id = d_idx[p];
        int i = id & 63, j = id >> 6;
        float d  = sh.dg[i] + sh.dg[j] - 2.f * sh.g[i * G_STR + j];
        float dc = sqrtf(fmaf(et, fmaxf(d, 0.f), 1e-5f));
        out[p] = dc - sh.rmv[i] - sh.rmv[j] + tmv;
    }
    if (tid < DIM)
        out[NSTRICT + tid] = sqrtf(1e-5f) - 2.f * sh.rmv[tid] + tmv;
}

// ============ class prototypes ============
__global__ __launch_bounds__(256) void k_redsup() {
    const int c = blockIdx.x;
    const int k = blockIdx.y * 256 + threadIdx.x;
    if (k >= NTRI) return;
    const float* base = d_tvsup + (size_t)c * PER_CLS * NTRI + k;
    float s = 0.f;
    #pragma unroll 8
    for (int si = 0; si < PER_CLS; ++si) s += base[(size_t)si * NTRI];
    d_support[c * NTRI + k] = s * (1.f / (float)PER_CLS);
}

__global__ __launch_bounds__(256) void k_s2() {
    const int c = blockIdx.x, tid = threadIdx.x;
    float a = 0.f;
    for (int k = tid; k < NTRI; k += 256) {
        float v = d_support[c * NTRI + k];
        a = fmaf(v, v, a);
    }
    __shared__ float wsum[8];
    #pragma unroll
    for (int off = 16; off; off >>= 1) a += __shfl_down_sync(0xffffffffu, a, off);
    if ((tid & 31) == 0) wsum[tid >> 5] = a;
    __syncthreads();
    if (tid == 0) {
        float t = 0.f;
        #pragma unroll
        for (int w = 0; w < 8; ++w) t += wsum[w];
        d_s2[c] = t;
    }
}

// ============ query: fused dq / q2 / cross ============
struct __align__(16) QShared {
    union {
        float xs [HW * XS_STR];   // live during gram
        float dqt[NSTRICT];       // packed strict-upper dq, live after
    } u;
    float g [DIM * G_STR];
    float dg[DIM];
    float rq[DIM];                // row means of dq
    float part[256];
    float tq;
    float wred[8][11];
};

__global__ __launch_bounds__(256) void k_query(const float* __restrict__ feat,
                                               const float* __restrict__ temp,
                                               float* __restrict__ score) {
    __shared__ QShared sh;
    const int q   = blockIdx.x;
    const int tid = threadIdx.x;
    const float et = expf(temp[0]);

    load_xs(feat + (size_t)(N_SUP + q) * (DIM * HW), sh.u.xs, tid);
    __syncthreads();
    gram64(sh.u.xs, sh.g, tid);
    __syncthreads();
    if (tid < DIM) sh.dg[tid] = sh.g[tid * G_STR + tid];
    __syncthreads();

    // dq pass: sqrt all 4096, row sums, pack strict upper into dqt (xs is dead)
    {
        const int i = tid & 63, grp = tid >> 6;
        const int jb = grp << 4;
        const float dgi = sh.dg[i];
        const int rowoff = (i * (127 - i)) >> 1;
        float s = 0.f;
        #pragma unroll
        for (int jj = 0; jj < 16; ++jj) {
            int j = jb + jj;
            float d  = dgi + sh.dg[j] - 2.f * sh.g[i * G_STR + j];
            float dq = sqrtf(fmaf(et, fmaxf(d, 0.f), 1e-5f));
            s += dq;
            if (j > i) sh.u.dqt[rowoff + j - i - 1] = dq;
        }
        sh.part[(grp << 6) + i] = s;
    }
    __syncthreads();
    if (tid < DIM) {
        float rs = sh.part[tid] + sh.part[64 + tid] + sh.part[128 + tid] + sh.part[192 + tid];
        sh.rq[tid] = rs * (1.f / 64.f);
    }
    __syncthreads();
    if (tid < 32) {
        float t2 = sh.rq[tid] + sh.rq[tid + 32];
        #pragma unroll
        for (int off = 16; off; off >>= 1) t2 += __shfl_down_sync(0xffffffffu, t2, off);
        if (tid == 0) sh.tq = t2 * (1.f / 64.f);
    }
    __syncthreads();
    const float tqv = sh.tq;

    // cross pass over strict upper, float4-vectorized (504 groups of 4)
    float accm[N_WAY];
    #pragma unroll
    for (int m = 0; m < N_WAY; ++m) accm[m] = 0.f;
    float q2a = 0.f;

    #pragma unroll
    for (int it = 0; it < 2; ++it) {
        int gidx = (it << 8) + tid;
        if (gidx < NSTRICT / 4) {
            int p = gidx << 2;
            ushort4 id4 = *(const ushort4*)(d_idx + p);
            float4  dq4 = *(const float4*)(sh.u.dqt + p);

            // q2 (centered values only needed here)
            {
                float v0 = dq4.x - sh.rq[id4.x & 63] - sh.rq[id4.x >> 6] + tqv;
                float v1 = dq4.y - sh.rq[id4.y & 63] - sh.rq[id4.y >> 6] + tqv;
                float v2 = dq4.z - sh.rq[id4.z & 63] - sh.rq[id4.z >> 6] + tqv;
                float v3 = dq4.w - sh.rq[id4.w & 63] - sh.rq[id4.w >> 6] + tqv;
                q2a = fmaf(v0, v0, q2a);
                q2a = fmaf(v1, v1, q2a);
                q2a = fmaf(v2, v2, q2a);
                q2a = fmaf(v3, v3, q2a);
            }
            // cross terms use RAW dq (support rows are zero-sum over full matrix)
            #pragma unroll
            for (int m = 0; m < N_WAY; ++m) {
                float4 sv = __ldg((const float4*)(d_support + m * NTRI + p));
                accm[m] = fmaf(dq4.x, sv.x, accm[m]);
                accm[m] = fmaf(dq4.y, sv.y, accm[m]);
                accm[m] = fmaf(dq4.z, sv.z, accm[m]);
                accm[m] = fmaf(dq4.w, sv.w, accm[m]);
            }
        }
    }

    // diagonal contributions folded into same accumulators
    if (tid < DIM) {
        float sq  = sqrtf(1e-5f);
        float rqi = sh.rq[tid];
        float vqd = sq - 2.f * rqi + tqv;          // centered diag value
        float w   = sq - rqi + 0.5f * tqv;          // 0.5*(dq_ii + vq_ii)
        q2a = fmaf(vqd, vqd, q2a);
        #pragma unroll
        for (int m = 0; m < N_WAY; ++m)
            accm[m] = fmaf(w, __ldg(d_support + m * NTRI + NSTRICT + tid), accm[m]);
    }

    // block reduction: 11 values
    #pragma unroll
    for (int off = 16; off; off >>= 1) {
        q2a += __shfl_down_sync(0xffffffffu, q2a, off);
        #pragma unroll
        for (int m = 0; m < N_WAY; ++m)
            accm[m] += __shfl_down_sync(0xffffffffu, accm[m], off);
    }
    if ((tid & 31) == 0) {
        int w = tid >> 5;
        sh.wred[w][10] = q2a;
        #pragma unroll
        for (int m = 0; m < N_WAY; ++m) sh.wred[w][m] = accm[m];
    }
    __syncthreads();
    if (tid == 0) {
        float q2 = 0.f;
        #pragma unroll
        for (int w = 0; w < 8; ++w) q2 += sh.wred[w][10];
        #pragma unroll
        for (int m = 0; m < N_WAY; ++m) {
            float dot = 0.f;
            #pragma unroll
            for (int w = 0; w < 8; ++w) dot += sh.wred[w][m];
            score[(size_t)q * N_WAY + m] = -(q2 + d_s2[m] - 2.f * dot);
        }
    }
}

// ============ loss ============
__global__ __launch_bounds__(256) void k_loss(const float* __restrict__ score,
                                              const void* __restrict__ label) {
    const int n   = blockIdx.x * 256 + threadIdx.x;
    const int tid = threadIdx.x;
    float val = 0.f;
    if (n < N_QRY) {
        float s[N_WAY];
        float mx = -1e30f;
        #pragma unroll
        for (int m = 0; m < N_WAY; ++m) {
            s[m] = score[(size_t)n * N_WAY + m];
            mx = fmaxf(mx, s[m]);
        }
        float se = 0.f;
        #pragma unroll
        for (int m = 0; m < N_WAY; ++m) se += expf(s[m] - mx);
        float lse = mx + logf(se);
        int lab = d_i64 ? (int)((const long long*)label)[n]
                        : ((const int*)label)[n];
        val = s[lab] - lse;
    }
    __shared__ float wsum[8];
    #pragma unroll
    for (int off = 16; off; off >>= 1) val += __shfl_down_sync(0xffffffffu, val, off);
    if ((tid & 31) == 0) wsum[tid >> 5] = val;
    __syncthreads();
    if (tid == 0) {
        float t = 0.f;
        #pragma unroll
        for (int w = 0; w < 8; ++w) t += wsum[w];
        d_partial[blockIdx.x] = t;
    }
}

__global__ void k_final(float* __restrict__ out, int nblk) {
    int tid = threadIdx.x;   // 32
    float s = 0.f;
    for (int idx = tid; idx < nblk; idx += 32) s += d_partial[idx];
    #pragma unroll
    for (int off = 16; off; off >>= 1) s += __shfl_down_sync(0xffffffffu, s, off);
    if (tid == 0) out[(size_t)N_QRY * N_WAY] = -s * (1.f / (float)N_QRY);
}

// ============ launch ============
extern "C" void kernel_launch(void* const* d_in, const int* in_sizes, int n_in,
                              void* d_out, int out_size) {
    const float* feat  = (const float*)d_in[0];
    const float* temp  = (const float*)d_in[1];
    const void*  label = d_in[2];
    float* out = (float*)d_out;
    (void)in_sizes; (void)n_in; (void)out_size;

    const int loss_blocks = (N_QRY + 255) / 256;   // 63

    k_idx    <<<1, 64>>>();
    k_flag   <<<1, 512>>>((const int*)label);
    k_support<<<N_SUP, 256>>>(feat, temp);
    k_redsup <<<dim3(N_WAY, (NTRI + 255) / 256), 256>>>();
    k_s2     <<<N_WAY, 256>>>();
    k_query  <<<N_QRY, 256>>>(feat, temp, out);
    k_loss   <<<loss_blocks, 256>>>(out, label);
    k_final  <<<1, 32>>>(out, loss_blocks);
}

// round 17
// speedup vs baseline: 1.1509x; 1.0001x over previous
#include <cuda_runtime.h>

#define N_WAY   10
#define DIM     64
#define HW      49
#define N_SUP   800
#define N_QRY   16000
#define NTRI    2080         // 64*65/2 (triu incl diag)
#define NSTRICT 2016         // strict upper triangle
#define PER_CLS 80
#define XS_STR  68           // padded row stride for xs
#define G_STR   65           // padded row stride for g (conflict-free columns)

// -------- device scratch (static globals; no allocations) --------
__device__ float d_tvsup[N_SUP * NTRI];     // per-support-sample packed tv (strict | diag)
__device__ float d_support[N_WAY * NTRI];   // prototypes, packed (strict 2016 | diag 64)
__device__ float d_s2[N_WAY];
__device__ float d_partial[64];
__device__ int   d_i64;
__device__ __align__(16) unsigned short d_idx[NSTRICT];  // packed (j<<6)|i per strict-p

// ============ shared helpers ============

__device__ __forceinline__ void load_xs(const float* __restrict__ fs,
                                        float* __restrict__ xs, int tid) {
    for (int idx = tid; idx < DIM * HW; idx += 256) {
        int i = idx / HW;
        int m = idx - i * HW;
        xs[m * XS_STR + i] = __ldg(fs + idx);
    }
}

// full 64x64 Gram from transposed xs; 16x16 grid of 4x4 register tiles
__device__ __forceinline__ void gram64(const float* __restrict__ xs,
                                       float* __restrict__ g, int tid) {
    const int i0 = (tid >> 4) << 2;
    const int j0 = (tid & 15) << 2;
    float acc[4][4];
    #pragma unroll
    for (int r = 0; r < 4; ++r)
        #pragma unroll
        for (int c = 0; c < 4; ++c) acc[r][c] = 0.f;

    const float* xrow = xs;
    #pragma unroll 7
    for (int m = 0; m < HW; ++m) {
        const float4 a = *(const float4*)(xrow + i0);
        const float4 b = *(const float4*)(xrow + j0);
        acc[0][0] = fmaf(a.x, b.x, acc[0][0]); acc[0][1] = fmaf(a.x, b.y, acc[0][1]);
        acc[0][2] = fmaf(a.x, b.z, acc[0][2]); acc[0][3] = fmaf(a.x, b.w, acc[0][3]);
        acc[1][0] = fmaf(a.y, b.x, acc[1][0]); acc[1][1] = fmaf(a.y, b.y, acc[1][1]);
        acc[1][2] = fmaf(a.y, b.z, acc[1][2]); acc[1][3] = fmaf(a.y, b.w, acc[1][3]);
        acc[2][0] = fmaf(a.z, b.x, acc[2][0]); acc[2][1] = fmaf(a.z, b.y, acc[2][1]);
        acc[2][2] = fmaf(a.z, b.z, acc[2][2]); acc[2][3] = fmaf(a.z, b.w, acc[2][3]);
        acc[3][0] = fmaf(a.w, b.x, acc[3][0]); acc[3][1] = fmaf(a.w, b.y, acc[3][1]);
        acc[3][2] = fmaf(a.w, b.z, acc[3][2]); acc[3][3] = fmaf(a.w, b.w, acc[3][3]);
        xrow += XS_STR;
    }
    #pragma unroll
    for (int r = 0; r < 4; ++r)
        #pragma unroll
        for (int c = 0; c < 4; ++c)
            g[(i0 + r) * G_STR + (j0 + c)] = acc[r][c];
}

// ============ init: strict-upper (i,j) index table ============
__global__ void k_idx() {
    int i = threadIdx.x;   // 64 threads
    if (i < 63) {
        int base = (i * (127 - i)) >> 1;
        for (int j = i + 1; j < 64; ++j)
            d_idx[base + j - i - 1] = (unsigned short)((j << 6) | i);
    }
}

// ============ label dtype detection ============
__global__ void k_flag(const int* __restrict__ lab32) {
    int tid = threadIdx.x;
    int f = 0;
    for (int idx = 1 + 2 * tid; idx < N_QRY; idx += 2 * 512)
        if (lab32[idx] != 0) f = 1;
    f = __syncthreads_or(f);
    if (tid == 0) d_i64 = f ? 0 : 1;
}

// ============ support: packed centered tv per sample ============
struct __align__(16) SupShared {
    float xs[HW * XS_STR];
    float g [DIM * G_STR];
    float dg[DIM];
    float rmv[DIM];
    float part[256];
    float tmv;
};

__global__ __launch_bounds__(256) void k_support(const float* __restrict__ feat,
                                                 const float* __restrict__ temp) {
    __shared__ SupShared sh;
    const int b   = blockIdx.x;
    const int tid = threadIdx.x;
    const float et = expf(temp[0]);

    load_xs(feat + (size_t)b * (DIM * HW), sh.xs, tid);
    __syncthreads();
    gram64(sh.xs, sh.g, tid);
    __syncthreads();
    if (tid < DIM) sh.dg[tid] = sh.g[tid * G_STR + tid];
    __syncthreads();

    // dcov row sums
    {
        const int i = tid & 63, grp = tid >> 6;
        const float dgi = sh.dg[i];
        float s = 0.f;
        #pragma unroll
        for (int jj = 0; jj < 16; ++jj) {
            int j = (grp << 4) + jj;
            float d = dgi + sh.dg[j] - 2.f * sh.g[i * G_STR + j];
            s += sqrtf(fmaf(et, fmaxf(d, 0.f), 1e-5f));
        }
        sh.part[(grp << 6) + i] = s;
    }
    __syncthreads();
    if (tid < DIM) {
        float rs = sh.part[tid] + sh.part[64 + tid] + sh.part[128 + tid] + sh.part[192 + tid];
        sh.rmv[tid] = rs * (1.f / 64.f);
    }
    __syncthreads();
    if (tid < 32) {
        float t2 = sh.rmv[tid] + sh.rmv[tid + 32];
        #pragma unroll
        for (int off = 16; off; off >>= 1) t2 += __shfl_down_sync(0xffffffffu, t2, off);
        if (tid == 0) sh.tmv = t2 * (1.f / 64.f);
    }
    __syncthreads();

    float* out = d_tvsup + (size_t)b * NTRI;
    const float tmv = sh.tmv;
    for (int p = tid; p < NSTRICT; p += 256) {
        unsigned short id = d_idx[p];
        int i = id & 63, j = id >> 6;
        float d  = sh.dg[i] + sh.dg[j] - 2.f * sh.g[i * G_STR + j];
        float dc = sqrtf(fmaf(et, fmaxf(d, 0.f), 1e-5f));
        out[p] = dc - sh.rmv[i] - sh.rmv[j] + tmv;
    }
    if (tid < DIM)
        out[NSTRICT + tid] = sqrtf(1e-5f) - 2.f * sh.rmv[tid] + tmv;
}

// ============ class prototypes ============
__global__ __launch_bounds__(256) void k_redsup() {
    const int c = blockIdx.x;
    const int k = blockIdx.y * 256 + threadIdx.x;
    if (k >= NTRI) return;
    const float* base = d_tvsup + (size_t)c * PER_CLS * NTRI + k;
    float s = 0.f;
    #pragma unroll 8
    for (int si = 0; si < PER_CLS; ++si) s += base[(size_t)si * NTRI];
    d_support[c * NTRI + k] = s * (1.f / (float)PER_CLS);
}

__global__ __launch_bounds__(256) void k_s2() {
    const int c = blockIdx.x, tid = threadIdx.x;
    float a = 0.f;
    for (int k = tid; k < NTRI; k += 256) {
        float v = d_support[c * NTRI + k];
        a = fmaf(v, v, a);
    }
    __shared__ float wsum[8];
    #pragma unroll
    for (int off = 16; off; off >>= 1) a += __shfl_down_sync(0xffffffffu, a, off);
    if ((tid & 31) == 0) wsum[tid >> 5] = a;
    __syncthreads();
    if (tid == 0) {
        float t = 0.f;
        #pragma unroll
        for (int w = 0; w < 8; ++w) t += wsum[w];
        d_s2[c] = t;
    }
}

// ============ query: fused dq / q2 / cross ============
struct __align__(16) QShared {
    union {
        float xs [HW * XS_STR];   // live during gram
        float dqt[NSTRICT];       // packed strict-upper dq, live after
    } u;
    float g [DIM * G_STR];
    float dg[DIM];
    float rq[DIM];                // row means of dq
    float part[256];
    float tq;
    float wred[8][11];
};

__global__ __launch_bounds__(256) void k_query(const float* __restrict__ feat,
                                               const float* __restrict__ temp,
                                               float* __restrict__ score) {
    __shared__ QShared sh;
    const int q   = blockIdx.x;
    const int tid = threadIdx.x;
    const float et = expf(temp[0]);

    load_xs(feat + (size_t)(N_SUP + q) * (DIM * HW), sh.u.xs, tid);
    __syncthreads();
    gram64(sh.u.xs, sh.g, tid);
    __syncthreads();
    if (tid < DIM) sh.dg[tid] = sh.g[tid * G_STR + tid];
    __syncthreads();

    // dq pass: sqrt all 4096, row sums, pack strict upper into dqt (xs is dead)
    {
        const int i = tid & 63, grp = tid >> 6;
        const int jb = grp << 4;
        const float dgi = sh.dg[i];
        const int rowoff = (i * (127 - i)) >> 1;
        float s = 0.f;
        #pragma unroll
        for (int jj = 0; jj < 16; ++jj) {
            int j = jb + jj;
            float d  = dgi + sh.dg[j] - 2.f * sh.g[i * G_STR + j];
            float dq = sqrtf(fmaf(et, fmaxf(d, 0.f), 1e-5f));
            s += dq;
            if (j > i) sh.u.dqt[rowoff + j - i - 1] = dq;
        }
        sh.part[(grp << 6) + i] = s;
    }
    __syncthreads();
    if (tid < DIM) {
        float rs = sh.part[tid] + sh.part[64 + tid] + sh.part[128 + tid] + sh.part[192 + tid];
        sh.rq[tid] = rs * (1.f / 64.f);
    }
    __syncthreads();
    if (tid < 32) {
        float t2 = sh.rq[tid] + sh.rq[tid + 32];
        #pragma unroll
        for (int off = 16; off; off >>= 1) t2 += __shfl_down_sync(0xffffffffu, t2, off);
        if (tid == 0) sh.tq = t2 * (1.f / 64.f);
    }
    __syncthreads();
    const float tqv = sh.tq;

    // cross pass over strict upper, float4-vectorized (504 groups of 4)
    float accm[N_WAY];
    #pragma unroll
    for (int m = 0; m < N_WAY; ++m) accm[m] = 0.f;
    float q2a = 0.f;

    #pragma unroll
    for (int it = 0; it < 2; ++it) {
        int gidx = (it << 8) + tid;
        if (gidx < NSTRICT / 4) {
            int p = gidx << 2;
            ushort4 id4 = *(const ushort4*)(d_idx + p);
            float4  dq4 = *(const float4*)(sh.u.dqt + p);

            // q2 (centered values only needed here)
            {
                float v0 = dq4.x - sh.rq[id4.x & 63] - sh.rq[id4.x >> 6] + tqv;
                float v1 = dq4.y - sh.rq[id4.y & 63] - sh.rq[id4.y >> 6] + tqv;
                float v2 = dq4.z - sh.rq[id4.z & 63] - sh.rq[id4.z >> 6] + tqv;
                float v3 = dq4.w - sh.rq[id4.w & 63] - sh.rq[id4.w >> 6] + tqv;
                q2a = fmaf(v0, v0, q2a);
                q2a = fmaf(v1, v1, q2a);
                q2a = fmaf(v2, v2, q2a);
                q2a = fmaf(v3, v3, q2a);
            }
            // cross terms use RAW dq (support rows are zero-sum over full matrix)
            #pragma unroll
            for (int m = 0; m < N_WAY; ++m) {
                float4 sv = __ldg((const float4*)(d_support + m * NTRI + p));
                accm[m] = fmaf(dq4.x, sv.x, accm[m]);
                accm[m] = fmaf(dq4.y, sv.y, accm[m]);
                accm[m] = fmaf(dq4.z, sv.z, accm[m]);
                accm[m] = fmaf(dq4.w, sv.w, accm[m]);
            }
        }
    }

    // diagonal contributions folded into same accumulators
    if (tid < DIM) {
        float sq  = sqrtf(1e-5f);
        float rqi = sh.rq[tid];
        float vqd = sq - 2.f * rqi + tqv;          // centered diag value
        float w   = sq - rqi + 0.5f * tqv;          // 0.5*(dq_ii + vq_ii)
        q2a = fmaf(vqd, vqd, q2a);
        #pragma unroll
        for (int m = 0; m < N_WAY; ++m)
            accm[m] = fmaf(w, __ldg(d_support + m * NTRI + NSTRICT + tid), accm[m]);
    }

    // block reduction: 11 values
    #pragma unroll
    for (int off = 16; off; off >>= 1) {
        q2a += __shfl_down_sync(0xffffffffu, q2a, off);
        #pragma unroll
        for (int m = 0; m < N_WAY; ++m)
            accm[m] += __shfl_down_sync(0xffffffffu, accm[m], off);
    }
    if ((tid & 31) == 0) {
        int w = tid >> 5;
        sh.wred[w][10] = q2a;
        #pragma unroll
        for (int m = 0; m < N_WAY; ++m) sh.wred[w][m] = accm[m];
    }
    __syncthreads();
    if (tid == 0) {
        float q2 = 0.f;
        #pragma unroll
        for (int w = 0; w < 8; ++w) q2 += sh.wred[w][10];
        #pragma unroll
        for (int m = 0; m < N_WAY; ++m) {
            float dot = 0.f;
            #pragma unroll
            for (int w = 0; w < 8; ++w) dot += sh.wred[w][m];
            score[(size_t)q * N_WAY + m] = -(q2 + d_s2[m] - 2.f * dot);
        }
    }
}

// ============ loss ============
__global__ __launch_bounds__(256) void k_loss(const float* __restrict__ score,
                                              const void* __restrict__ label) {
    const int n   = blockIdx.x * 256 + threadIdx.x;
    const int tid = threadIdx.x;
    float val = 0.f;
    if (n < N_QRY) {
        float s[N_WAY];
        float mx = -1e30f;
        #pragma unroll
        for (int m = 0; m < N_WAY; ++m) {
            s[m] = score[(size_t)n * N_WAY + m];
            mx = fmaxf(mx, s[m]);
        }
        float se = 0.f;
        #pragma unroll
        for (int m = 0; m < N_WAY; ++m) se += expf(s[m] - mx);
        float lse = mx + logf(se);
        int lab = d_i64 ? (int)((const long long*)label)[n]
                        : ((const int*)label)[n];
        val = s[lab] - lse;
    }
    __shared__ float wsum[8];
    #pragma unroll
    for (int off = 16; off; off >>= 1) val += __shfl_down_sync(0xffffffffu, val, off);
    if ((tid & 31) == 0) wsum[tid >> 5] = val;
    __syncthreads();
    if (tid == 0) {
        float t = 0.f;
        #pragma unroll
        for (int w = 0; w < 8; ++w) t += wsum[w];
        d_partial[blockIdx.x] = t;
    }
}

__global__ void k_final(float* __restrict__ out, int nblk) {
    int tid = threadIdx.x;   // 32
    float s = 0.f;
    for (int idx = tid; idx < nblk; idx += 32) s += d_partial[idx];
    #pragma unroll
    for (int off = 16; off; off >>= 1) s += __shfl_down_sync(0xffffffffu, s, off);
    if (tid == 0) out[(size_t)N_QRY * N_WAY] = -s * (1.f / (float)N_QRY);
}

// ============ launch ============
extern "C" void kernel_launch(void* const* d_in, const int* in_sizes, int n_in,
                              void* d_out, int out_size) {
    const float* feat  = (const float*)d_in[0];
    const float* temp  = (const float*)d_in[1];
    const void*  label = d_in[2];
    float* out = (float*)d_out;
    (void)in_sizes; (void)n_in; (void)out_size;

    const int loss_blocks = (N_QRY + 255) / 256;   // 63

    k_idx    <<<1, 64>>>();
    k_flag   <<<1, 512>>>((const int*)label);
    k_support<<<N_SUP, 256>>>(feat, temp);
    k_redsup <<<dim3(N_WAY, (NTRI + 255) / 256), 256>>>();
    k_s2     <<<N_WAY, 256>>>();
    k_query  <<<N_QRY, 256>>>(feat, temp, out);
    k_loss   <<<loss_blocks, 256>>>(out, label);
    k_final  <<<1, 32>>>(out, loss_blocks);
}